// round 7
// baseline (speedup 1.0000x reference)
#include <cuda_runtime.h>
#include <cstdint>
#include <cstddef>

#define T_LEN 512
#define BATCH 64
#define ISZ   256
#define HID   512
#define NCOL  2048      // 4*HID
#define GRID2 128       // persistent blocks, 1/SM, all co-resident

// ---------------- device scratch ----------------
__device__ float g_gx[(size_t)T_LEN * NCOL * BATCH];   // [T][2048][64], bx+bh folded in
__device__ float g_h[2][BATCH * HID];                  // h double buffer
__device__ unsigned g_done[GRID2];                     // per-block step counters (distributed barrier)

// ---------------- packed fp32x2 FMA ----------------
__device__ __forceinline__ unsigned long long fma2(unsigned long long a,
                                                   unsigned long long b,
                                                   unsigned long long c) {
    unsigned long long d;
    asm("fma.rn.f32x2 %0, %1, %2, %3;" : "=l"(d) : "l"(a), "l"(b), "l"(c));
    return d;
}
__device__ __forceinline__ float hsum2(unsigned long long v) {
    float lo, hi;
    asm("mov.b64 {%0,%1}, %2;" : "=f"(lo), "=f"(hi) : "l"(v));
    return lo + hi;
}
__device__ __forceinline__ float sigf(float x) {
    return 1.0f / (1.0f + __expf(-x));
}
__device__ __forceinline__ float tanh_acc(float x) {
    float ax = fabsf(x);
    float e  = __expf(-2.0f * ax);
    float r  = (1.0f - e) / (1.0f + e);
    return copysignf(r, x);
}

// =====================================================================
// Phase 1 (proven): gx[t][n][b] = x[t,b,:]·Wx[n,:] + bx[n]+bh[n]
//   Also resets the phase-2 done slots (stream order guarantees safety).
// =====================================================================
#define P1_PAD 132

extern "C" __global__ void __launch_bounds__(256, 2)
lstm_phase1(const float* __restrict__ x, const float* __restrict__ Wx,
            const float* __restrict__ bx, const float* __restrict__ bh)
{
    extern __shared__ float smem[];
    float* xs   = smem;
    float* ws   = smem + 64 * P1_PAD;
    float* sbuf = smem;

    const int t   = blockIdx.y;
    const int n0  = blockIdx.x * 64;
    const int tid = threadIdx.x;
    const int nq  = tid & 15;
    const int bq  = tid >> 4;

    if (blockIdx.x == 0 && blockIdx.y == 0 && tid < GRID2) g_done[tid] = 0u;

    unsigned long long acc[4][4];
    #pragma unroll
    for (int a = 0; a < 4; a++)
        #pragma unroll
        for (int c = 0; c < 4; c++) acc[a][c] = 0ull;

    #pragma unroll
    for (int ks = 0; ks < 2; ks++) {
        const int k0 = ks * 128;
        __syncthreads();
        for (int e = tid; e < 64 * 32; e += 256) {
            int bb = e >> 5, kq = e & 31;
            float4 v = *reinterpret_cast<const float4*>(
                &x[((size_t)t * BATCH + bb) * ISZ + k0 + kq * 4]);
            *reinterpret_cast<float4*>(&xs[bb * P1_PAD + kq * 4]) = v;
        }
        for (int e = tid; e < 64 * 32; e += 256) {
            int r = e >> 5, kq = e & 31;
            float4 v = *reinterpret_cast<const float4*>(
                &Wx[(size_t)(n0 + r) * ISZ + k0 + kq * 4]);
            *reinterpret_cast<float4*>(&ws[r * P1_PAD + kq * 4]) = v;
        }
        __syncthreads();

        #pragma unroll 4
        for (int k4 = 0; k4 < 128; k4 += 4) {
            ulonglong2 xv[4], wv[4];
            #pragma unroll
            for (int rb = 0; rb < 4; rb++)
                xv[rb] = *reinterpret_cast<const ulonglong2*>(
                    &xs[(bq + 16 * rb) * P1_PAD + k4]);
            #pragma unroll
            for (int rn = 0; rn < 4; rn++)
                wv[rn] = *reinterpret_cast<const ulonglong2*>(
                    &ws[(nq + 16 * rn) * P1_PAD + k4]);
            #pragma unroll
            for (int rb = 0; rb < 4; rb++)
                #pragma unroll
                for (int rn = 0; rn < 4; rn++) {
                    acc[rb][rn] = fma2(xv[rb].x, wv[rn].x, acc[rb][rn]);
                    acc[rb][rn] = fma2(xv[rb].y, wv[rn].y, acc[rb][rn]);
                }
        }
    }
    __syncthreads();

    #pragma unroll
    for (int rb = 0; rb < 4; rb++)
        #pragma unroll
        for (int rn = 0; rn < 4; rn++)
            sbuf[(nq + 16 * rn) * 68 + (bq + 16 * rb)] = hsum2(acc[rb][rn]);
    __syncthreads();

    for (int e = tid; e < 64 * 16; e += 256) {
        int row = e >> 4, c4 = e & 15;
        int n = n0 + row;
        float bias = bx[n] + bh[n];
        float4 v = *reinterpret_cast<float4*>(&sbuf[row * 68 + c4 * 4]);
        v.x += bias; v.y += bias; v.z += bias; v.w += bias;
        *reinterpret_cast<float4*>(
            &g_gx[((size_t)t * NCOL + n) * BATCH + c4 * 4]) = v;
    }
}

// =====================================================================
// Phase 2: persistent recurrence, R2-proven protocol with a distributed
// grid barrier (per-block slots instead of one serialized atomic chain).
// 128 blocks x 512 threads. thread = (kh, b, jj).
// =====================================================================
#define HS_PAD 516
#define WS_PAD 520
#define NTHR2  512

__device__ __forceinline__ void cpa_commit() {
    asm volatile("cp.async.commit_group;" ::: "memory");
}
template <int N>
__device__ __forceinline__ void cpa_wait() {
    asm volatile("cp.async.wait_group %0;" :: "n"(N) : "memory");
}

__device__ __forceinline__ void warp_copy_chunk(float* hs, const float* hsrc,
                                                int b0, int kofs, int lane) {
    #pragma unroll
    for (int p = lane; p < 256; p += 32) {
        int r  = p >> 5;
        int kq = p & 31;
        unsigned dst = (unsigned)__cvta_generic_to_shared(
            &hs[(b0 + r) * HS_PAD + kofs + kq * 4]);
        const float* src = &hsrc[(size_t)(b0 + r) * HID + kofs + kq * 4];
        asm volatile("cp.async.cg.shared.global [%0], [%1], 16;"
                     :: "r"(dst), "l"(src) : "memory");
    }
}

__device__ __forceinline__ void dot_chunk(const float* __restrict__ hrow,
                                          const float* __restrict__ ws,
                                          int jj, int kofs,
                                          unsigned long long accx[4],
                                          unsigned long long accy[4]) {
    #pragma unroll 4
    for (int k4 = 0; k4 < 128; k4 += 4) {
        ulonglong2 h2 = *reinterpret_cast<const ulonglong2*>(&hrow[kofs + k4]);
        #pragma unroll
        for (int g = 0; g < 4; g++) {
            ulonglong2 w2 = *reinterpret_cast<const ulonglong2*>(
                &ws[(g * 4 + jj) * WS_PAD + kofs + k4]);
            accx[g] = fma2(h2.x, w2.x, accx[g]);
            accy[g] = fma2(h2.y, w2.y, accy[g]);
        }
    }
}

extern "C" __global__ void __launch_bounds__(NTHR2, 1)
lstm_phase2(const float* __restrict__ Wh, float* __restrict__ out)
{
    extern __shared__ float smem[];
    float* hs  = smem;                              // [64][516]
    float* ws  = smem + 64 * HS_PAD;                // [16][520]
    float* red = smem + 64 * HS_PAD + 16 * WS_PAD;  // [256][4]

    const int tid  = threadIdx.x;
    const int bid  = blockIdx.x;
    const int lane = tid & 31;
    const int kh   = tid >> 8;                  // 0/1: k-half
    const int t8   = tid & 255;
    const int b    = t8 >> 2;                   // 0..63
    const int jj   = t8 & 3;                    // 0..3
    const int j    = bid * 4 + jj;
    const int wb0  = ((tid >> 5) & 7) * 8;      // first b-row of this warp
    const int kA   = kh * 256;                  // warp's first chunk
    const int kB   = kA + 128;                  // warp's second chunk

    // Wh slice resident for all steps
    for (int e = tid; e < 16 * 128; e += NTHR2) {
        int row = e >> 7, kq = e & 127;
        int g = row >> 2, jx = row & 3;
        float4 v = *reinterpret_cast<const float4*>(
            &Wh[((size_t)(g * HID + bid * 4 + jx)) * HID + kq * 4]);
        *reinterpret_cast<float4*>(&ws[row * WS_PAD + kq * 4]) = v;
    }
    float c_state = 0.0f;
    __syncthreads();   // ws ready

    for (int t = 0; t < T_LEN; t++) {
        const int rb = t & 1;
        const int wbuf = rb ^ 1;

        // gx prefetch FIRST — independent of h, hides LDG under the wait below
        float gxv[4] = {0.f, 0.f, 0.f, 0.f};
        if (kh == 0) {
            #pragma unroll
            for (int g = 0; g < 4; g++)
                gxv[g] = g_gx[((size_t)t * NCOL + g * HID + j) * BATCH + b];
        }

        unsigned long long accx[4] = {0ull, 0ull, 0ull, 0ull};
        unsigned long long accy[4] = {0ull, 0ull, 0ull, 0ull};

        if (t > 0) {
            // -------- distributed barrier wait: all 128 slots >= t --------
            if (tid < 32) {
                const unsigned need = (unsigned)t;
                bool ok;
                do {
                    unsigned v0, v1, v2, v3;
                    asm volatile("ld.relaxed.gpu.global.u32 %0, [%1];"
                                 : "=r"(v0) : "l"(&g_done[lane]) : "memory");
                    asm volatile("ld.relaxed.gpu.global.u32 %0, [%1];"
                                 : "=r"(v1) : "l"(&g_done[lane + 32]) : "memory");
                    asm volatile("ld.relaxed.gpu.global.u32 %0, [%1];"
                                 : "=r"(v2) : "l"(&g_done[lane + 64]) : "memory");
                    asm volatile("ld.relaxed.gpu.global.u32 %0, [%1];"
                                 : "=r"(v3) : "l"(&g_done[lane + 96]) : "memory");
                    bool mine = ((int)(v0 - need) >= 0) & ((int)(v1 - need) >= 0)
                              & ((int)(v2 - need) >= 0) & ((int)(v3 - need) >= 0);
                    ok = __all_sync(0xFFFFFFFFu, mine);
                } while (!ok);
                asm volatile("fence.acq_rel.gpu;" ::: "memory");
            }
            __syncthreads();   // everyone gated on h(t-1) ready

            const float* hsrc = g_h[rb];
            warp_copy_chunk(hs, hsrc, wb0, kA, lane); cpa_commit();
            warp_copy_chunk(hs, hsrc, wb0, kB, lane); cpa_commit();
            const float* hrow = &hs[b * HS_PAD];
            cpa_wait<1>();
            dot_chunk(hrow, ws, jj, kA, accx, accy);
            cpa_wait<0>();
            dot_chunk(hrow, ws, jj, kB, accx, accy);
        }

        float part[4];
        #pragma unroll
        for (int g = 0; g < 4; g++) part[g] = hsum2(accx[g]) + hsum2(accy[g]);

        if (kh == 1) {
            *reinterpret_cast<float4*>(&red[t8 * 4]) =
                make_float4(part[0], part[1], part[2], part[3]);
        }
        __syncthreads();   // partials visible; hs/red WAR-safe (R2 protocol)

        if (kh == 0) {
            float4 pv = *reinterpret_cast<float4*>(&red[t8 * 4]);
            float gate0 = part[0] + pv.x + gxv[0];
            float gate1 = part[1] + pv.y + gxv[1];
            float gate2 = part[2] + pv.z + gxv[2];
            float gate3 = part[3] + pv.w + gxv[3];

            float f  = sigf(gate0);
            float i  = sigf(gate1);
            float o  = sigf(gate2);
            float cc = tanh_acc(gate3);
            c_state  = f * c_state + i * cc;
            float h  = o * tanh_acc(c_state);

            g_h[wbuf][b * HID + j] = h;
            out[((size_t)t * BATCH + b) * HID + j] = h;
            if (t == T_LEN - 1) {
                out[(size_t)T_LEN * BATCH * HID + (size_t)b * HID + j] = h;
                out[(size_t)T_LEN * BATCH * HID + (size_t)BATCH * HID
                    + (size_t)b * HID + j] = c_state;
            }
            __threadfence();   // my h stores -> gpu scope before arrival
        }
        __syncthreads();       // all h(t) stores done block-wide

        if (tid == 0) {
            __threadfence();   // cumulativity: block's stores before release
            asm volatile("st.release.gpu.global.u32 [%0], %1;"
                         :: "l"(&g_done[bid]), "r"((unsigned)(t + 1)) : "memory");
        }
        // no trailing sync needed: next iteration's poll+syncthreads gates reads
    }
}

// =====================================================================
// launch
// =====================================================================
extern "C" void kernel_launch(void* const* d_in, const int* in_sizes, int n_in,
                              void* d_out, int out_size) {
    (void)in_sizes; (void)n_in; (void)out_size;
    const float* x  = (const float*)d_in[0];
    const float* Wx = (const float*)d_in[1];
    const float* bx = (const float*)d_in[2];
    const float* Wh = (const float*)d_in[3];
    const float* bh = (const float*)d_in[4];
    float* out = (float*)d_out;

    const int smem1 = 2 * 64 * P1_PAD * sizeof(float);
    const int smem2 = (64 * HS_PAD + 16 * WS_PAD + 256 * 4) * sizeof(float);
    cudaFuncSetAttribute(lstm_phase1, cudaFuncAttributeMaxDynamicSharedMemorySize, smem1);
    cudaFuncSetAttribute(lstm_phase2, cudaFuncAttributeMaxDynamicSharedMemorySize, smem2);

    dim3 g1(32, T_LEN);
    lstm_phase1<<<g1, 256, smem1>>>(x, Wx, bx, bh);
    lstm_phase2<<<GRID2, NTHR2, smem2>>>(Wh, out);
}

// round 10
// speedup vs baseline: 1.2678x; 1.2678x over previous
#include <cuda_runtime.h>
#include <cstdint>
#include <cstddef>

#define T_LEN 512
#define BATCH 64
#define ISZ   256
#define HID   512
#define NCOL  2048      // 4*HID
#define GRID2 128       // persistent blocks, 1/SM, all co-resident

// ---------------- device scratch ----------------
__device__ float g_gx[(size_t)T_LEN * NCOL * BATCH];   // [T][2048][64], bx+bh folded in
__device__ float g_h[2][BATCH * HID];                  // h double buffer
__device__ unsigned g_done[GRID2];                     // per-block step counters

// ---------------- packed fp32x2 FMA ----------------
__device__ __forceinline__ unsigned long long fma2(unsigned long long a,
                                                   unsigned long long b,
                                                   unsigned long long c) {
    unsigned long long d;
    asm("fma.rn.f32x2 %0, %1, %2, %3;" : "=l"(d) : "l"(a), "l"(b), "l"(c));
    return d;
}
__device__ __forceinline__ float hsum2(unsigned long long v) {
    float lo, hi;
    asm("mov.b64 {%0,%1}, %2;" : "=f"(lo), "=f"(hi) : "l"(v));
    return lo + hi;
}
__device__ __forceinline__ float sigf(float x) {
    return 1.0f / (1.0f + __expf(-x));
}
__device__ __forceinline__ float tanh_acc(float x) {
    float ax = fabsf(x);
    float e  = __expf(-2.0f * ax);
    float r  = (1.0f - e) / (1.0f + e);
    return copysignf(r, x);
}

// =====================================================================
// Phase 1 (proven): gx[t][n][b] = x[t,b,:]·Wx[n,:] + bx[n]+bh[n]
//   Also resets the phase-2 done slots (stream order guarantees safety).
// =====================================================================
#define P1_PAD 132

extern "C" __global__ void __launch_bounds__(256, 2)
lstm_phase1(const float* __restrict__ x, const float* __restrict__ Wx,
            const float* __restrict__ bx, const float* __restrict__ bh)
{
    extern __shared__ float smem[];
    float* xs   = smem;
    float* ws   = smem + 64 * P1_PAD;
    float* sbuf = smem;

    const int t   = blockIdx.y;
    const int n0  = blockIdx.x * 64;
    const int tid = threadIdx.x;
    const int nq  = tid & 15;
    const int bq  = tid >> 4;

    if (blockIdx.x == 0 && blockIdx.y == 0 && tid < GRID2) g_done[tid] = 0u;

    unsigned long long acc[4][4];
    #pragma unroll
    for (int a = 0; a < 4; a++)
        #pragma unroll
        for (int c = 0; c < 4; c++) acc[a][c] = 0ull;

    #pragma unroll
    for (int ks = 0; ks < 2; ks++) {
        const int k0 = ks * 128;
        __syncthreads();
        for (int e = tid; e < 64 * 32; e += 256) {
            int bb = e >> 5, kq = e & 31;
            float4 v = *reinterpret_cast<const float4*>(
                &x[((size_t)t * BATCH + bb) * ISZ + k0 + kq * 4]);
            *reinterpret_cast<float4*>(&xs[bb * P1_PAD + kq * 4]) = v;
        }
        for (int e = tid; e < 64 * 32; e += 256) {
            int r = e >> 5, kq = e & 31;
            float4 v = *reinterpret_cast<const float4*>(
                &Wx[(size_t)(n0 + r) * ISZ + k0 + kq * 4]);
            *reinterpret_cast<float4*>(&ws[r * P1_PAD + kq * 4]) = v;
        }
        __syncthreads();

        #pragma unroll 4
        for (int k4 = 0; k4 < 128; k4 += 4) {
            ulonglong2 xv[4], wv[4];
            #pragma unroll
            for (int rb = 0; rb < 4; rb++)
                xv[rb] = *reinterpret_cast<const ulonglong2*>(
                    &xs[(bq + 16 * rb) * P1_PAD + k4]);
            #pragma unroll
            for (int rn = 0; rn < 4; rn++)
                wv[rn] = *reinterpret_cast<const ulonglong2*>(
                    &ws[(nq + 16 * rn) * P1_PAD + k4]);
            #pragma unroll
            for (int rb = 0; rb < 4; rb++)
                #pragma unroll
                for (int rn = 0; rn < 4; rn++) {
                    acc[rb][rn] = fma2(xv[rb].x, wv[rn].x, acc[rb][rn]);
                    acc[rb][rn] = fma2(xv[rb].y, wv[rn].y, acc[rb][rn]);
                }
        }
    }
    __syncthreads();

    #pragma unroll
    for (int rb = 0; rb < 4; rb++)
        #pragma unroll
        for (int rn = 0; rn < 4; rn++)
            sbuf[(nq + 16 * rn) * 68 + (bq + 16 * rb)] = hsum2(acc[rb][rn]);
    __syncthreads();

    for (int e = tid; e < 64 * 16; e += 256) {
        int row = e >> 4, c4 = e & 15;
        int n = n0 + row;
        float bias = bx[n] + bh[n];
        float4 v = *reinterpret_cast<float4*>(&sbuf[row * 68 + c4 * 4]);
        v.x += bias; v.y += bias; v.z += bias; v.w += bias;
        *reinterpret_cast<float4*>(
            &g_gx[((size_t)t * NCOL + n) * BATCH + c4 * 4]) = v;
    }
}

// =====================================================================
// Phase 2: persistent recurrence. 128 blocks x 512 threads.
//   thread = (kq, bp, jj): kq = k-quarter (0..3), handles batches bp and bp+32,
//   4 gates for unit j = bid*4+jj over 128 k.
//   Sync protocol identical to R7 (proven): distributed slots + backoff poll,
//   poll->fence->syncthreads gate; out stores AFTER release (off critical path).
// =====================================================================
#define HS_PAD 516
#define WS_PAD 520
#define NTHR2  512

__device__ __forceinline__ void cpa_commit() {
    asm volatile("cp.async.commit_group;" ::: "memory");
}
template <int N>
__device__ __forceinline__ void cpa_wait() {
    asm volatile("cp.async.wait_group %0;" :: "n"(N) : "memory");
}

// copy 16 rows (8 at brow0, 8 at brow0+32) x 64 floats at kofs, by one warp
__device__ __forceinline__ void warp_copy16(float* hs, const float* hsrc,
                                            int brow0, int kofs, int lane) {
    #pragma unroll
    for (int i = 0; i < 8; i++) {
        int p   = lane + i * 32;           // 0..255
        int grp = p >> 7;                  // 0/1
        int rr  = (p >> 4) & 7;            // 0..7
        int cc  = p & 15;                  // 0..15 (x4 floats)
        int row = brow0 + grp * 32 + rr;
        unsigned dst = (unsigned)__cvta_generic_to_shared(
            &hs[row * HS_PAD + kofs + cc * 4]);
        const float* src = &hsrc[(size_t)row * HID + kofs + cc * 4];
        asm volatile("cp.async.cg.shared.global [%0], [%1], 16;"
                     :: "r"(dst), "l"(src) : "memory");
    }
}

// 64-k sub-chunk dot for 2 batch rows x 4 gates
__device__ __forceinline__ void dot_sub(const float* __restrict__ hs,
                                        const float* __restrict__ ws,
                                        int b0, int jj, int kofs,
                                        unsigned long long accA[4],
                                        unsigned long long accB[4]) {
    const float* hr0 = &hs[b0 * HS_PAD + kofs];
    const float* hr1 = &hs[(b0 + 32) * HS_PAD + kofs];
    #pragma unroll 4
    for (int k4 = 0; k4 < 64; k4 += 4) {
        ulonglong2 ha = *reinterpret_cast<const ulonglong2*>(&hr0[k4]);
        ulonglong2 hb = *reinterpret_cast<const ulonglong2*>(&hr1[k4]);
        #pragma unroll
        for (int g = 0; g < 4; g++) {
            ulonglong2 w2 = *reinterpret_cast<const ulonglong2*>(
                &ws[(g * 4 + jj) * WS_PAD + kofs + k4]);
            accA[g] = fma2(ha.x, w2.x, accA[g]);
            accA[g] = fma2(ha.y, w2.y, accA[g]);
            accB[g] = fma2(hb.x, w2.x, accB[g]);
            accB[g] = fma2(hb.y, w2.y, accB[g]);
        }
    }
}

extern "C" __global__ void __launch_bounds__(NTHR2, 1)
lstm_phase2(const float* __restrict__ Wh, float* __restrict__ out)
{
    extern __shared__ float smem[];
    float* hs  = smem;                              // [64][516]
    float* ws  = smem + 64 * HS_PAD;                // [16][520]
    float* red = smem + 64 * HS_PAD + 16 * WS_PAD;  // [3][64][4][4]

    const int tid  = threadIdx.x;
    const int bid  = blockIdx.x;
    const int lane = tid & 31;
    const int kq   = tid >> 7;                  // 0..3: k-quarter
    const int r7   = tid & 127;
    const int bp   = r7 >> 2;                   // 0..31 -> batches bp, bp+32
    const int jj   = r7 & 3;                    // 0..3
    const int j    = bid * 4 + jj;
    const int wq   = (tid >> 5) & 3;            // warp-in-quarter
    const int brow0 = wq * 8;                   // warp's first b row (and +32)
    const int kofs = kq * 128;                  // thread's k base

    // Wh slice resident for all steps
    for (int e = tid; e < 16 * 128; e += NTHR2) {
        int row = e >> 7, kk = e & 127;
        int g = row >> 2, jx = row & 3;
        float4 v = *reinterpret_cast<const float4*>(
            &Wh[((size_t)(g * HID + bid * 4 + jx)) * HID + kk * 4]);
        *reinterpret_cast<float4*>(&ws[row * WS_PAD + kk * 4]) = v;
    }
    float c0 = 0.0f, c1 = 0.0f;
    __syncthreads();   // ws ready

    for (int t = 0; t < T_LEN; t++) {
        const int rb = t & 1;
        const int wbuf = rb ^ 1;

        // gx prefetch first — independent of h, hides LDG under the poll
        float gxa[4], gxb[4];
        if (kq == 0) {
            #pragma unroll
            for (int g = 0; g < 4; g++) {
                size_t base = ((size_t)t * NCOL + g * HID + j) * BATCH;
                gxa[g] = g_gx[base + bp];
                gxb[g] = g_gx[base + bp + 32];
            }
        }

        unsigned long long accA[4] = {0ull, 0ull, 0ull, 0ull};
        unsigned long long accB[4] = {0ull, 0ull, 0ull, 0ull};

        if (t > 0) {
            // ---- distributed barrier wait (with backoff): all slots >= t ----
            if (tid < 32) {
                const unsigned need = (unsigned)t;
                bool ok;
                do {
                    unsigned v0, v1, v2, v3;
                    asm volatile("ld.relaxed.gpu.global.u32 %0, [%1];"
                                 : "=r"(v0) : "l"(&g_done[lane]) : "memory");
                    asm volatile("ld.relaxed.gpu.global.u32 %0, [%1];"
                                 : "=r"(v1) : "l"(&g_done[lane + 32]) : "memory");
                    asm volatile("ld.relaxed.gpu.global.u32 %0, [%1];"
                                 : "=r"(v2) : "l"(&g_done[lane + 64]) : "memory");
                    asm volatile("ld.relaxed.gpu.global.u32 %0, [%1];"
                                 : "=r"(v3) : "l"(&g_done[lane + 96]) : "memory");
                    bool mine = ((int)(v0 - need) >= 0) & ((int)(v1 - need) >= 0)
                              & ((int)(v2 - need) >= 0) & ((int)(v3 - need) >= 0);
                    ok = __all_sync(0xFFFFFFFFu, mine);
                    if (!ok) __nanosleep(20);
                } while (!ok);
                asm volatile("fence.acq_rel.gpu;" ::: "memory");
            }
            __syncthreads();   // everyone gated on h(t-1) ready

            const float* hsrc = g_h[rb];
            warp_copy16(hs, hsrc, brow0, kofs, lane);      cpa_commit();
            warp_copy16(hs, hsrc, brow0, kofs + 64, lane); cpa_commit();
            cpa_wait<1>();
            dot_sub(hs, ws, bp, jj, kofs, accA, accB);
            cpa_wait<0>();
            dot_sub(hs, ws, bp, jj, kofs + 64, accA, accB);
        }

        float pa[4], pb[4];
        #pragma unroll
        for (int g = 0; g < 4; g++) { pa[g] = hsum2(accA[g]); pb[g] = hsum2(accB[g]); }

        if (kq != 0) {
            float* ra = &red[(((kq - 1) * 64 + bp) * 4 + jj) * 4];
            float* rbp = &red[(((kq - 1) * 64 + bp + 32) * 4 + jj) * 4];
            *reinterpret_cast<float4*>(ra)  = make_float4(pa[0], pa[1], pa[2], pa[3]);
            *reinterpret_cast<float4*>(rbp) = make_float4(pb[0], pb[1], pb[2], pb[3]);
        }
        __syncthreads();   // partials visible (hs/red WAR gated by own-release order)

        float h0 = 0.f, h1 = 0.f;
        if (kq == 0) {
            #pragma unroll
            for (int q = 0; q < 3; q++) {
                float4 va = *reinterpret_cast<float4*>(
                    &red[((q * 64 + bp) * 4 + jj) * 4]);
                float4 vb = *reinterpret_cast<float4*>(
                    &red[((q * 64 + bp + 32) * 4 + jj) * 4]);
                pa[0] += va.x; pa[1] += va.y; pa[2] += va.z; pa[3] += va.w;
                pb[0] += vb.x; pb[1] += vb.y; pb[2] += vb.z; pb[3] += vb.w;
            }
            {
                float f  = sigf(pa[0] + gxa[0]);
                float i  = sigf(pa[1] + gxa[1]);
                float o  = sigf(pa[2] + gxa[2]);
                float cc = tanh_acc(pa[3] + gxa[3]);
                c0 = f * c0 + i * cc;
                h0 = o * tanh_acc(c0);
            }
            {
                float f  = sigf(pb[0] + gxb[0]);
                float i  = sigf(pb[1] + gxb[1]);
                float o  = sigf(pb[2] + gxb[2]);
                float cc = tanh_acc(pb[3] + gxb[3]);
                c1 = f * c1 + i * cc;
                h1 = o * tanh_acc(c1);
            }
            g_h[wbuf][bp * HID + j]        = h0;
            g_h[wbuf][(bp + 32) * HID + j] = h1;
            __threadfence();   // drains ONLY the two g_h stores (out not yet issued)
        }
        __syncthreads();       // all h(t) stores done block-wide

        if (tid == 0) {
            __threadfence();   // cumulativity: block's stores before release
            asm volatile("st.release.gpu.global.u32 [%0], %1;"
                         :: "l"(&g_done[bid]), "r"((unsigned)(t + 1)) : "memory");
        }

        // out stores AFTER release — off the recurrence critical path
        if (kq == 0) {
            out[((size_t)t * BATCH + bp) * HID + j]        = h0;
            out[((size_t)t * BATCH + bp + 32) * HID + j]   = h1;
            if (t == T_LEN - 1) {
                size_t ofs = (size_t)T_LEN * BATCH * HID;
                out[ofs + (size_t)bp * HID + j]        = h0;
                out[ofs + (size_t)(bp + 32) * HID + j] = h1;
                ofs += (size_t)BATCH * HID;
                out[ofs + (size_t)bp * HID + j]        = c0;
                out[ofs + (size_t)(bp + 32) * HID + j] = c1;
            }
        }
        // next iteration's poll+syncthreads gates all cross-step reads
    }
}

// =====================================================================
// launch
// =====================================================================
extern "C" void kernel_launch(void* const* d_in, const int* in_sizes, int n_in,
                              void* d_out, int out_size) {
    (void)in_sizes; (void)n_in; (void)out_size;
    const float* x  = (const float*)d_in[0];
    const float* Wx = (const float*)d_in[1];
    const float* bx = (const float*)d_in[2];
    const float* Wh = (const float*)d_in[3];
    const float* bh = (const float*)d_in[4];
    float* out = (float*)d_out;

    const int smem1 = 2 * 64 * P1_PAD * sizeof(float);
    const int smem2 = (64 * HS_PAD + 16 * WS_PAD + 3 * 64 * 4 * 4) * sizeof(float);
    cudaFuncSetAttribute(lstm_phase1, cudaFuncAttributeMaxDynamicSharedMemorySize, smem1);
    cudaFuncSetAttribute(lstm_phase2, cudaFuncAttributeMaxDynamicSharedMemorySize, smem2);

    dim3 g1(32, T_LEN);
    lstm_phase1<<<g1, 256, smem1>>>(x, Wx, bx, bh);
    lstm_phase2<<<GRID2, NTHR2, smem2>>>(Wh, out);
}

// round 11
// speedup vs baseline: 1.4522x; 1.1454x over previous
#include <cuda_runtime.h>
#include <cstdint>
#include <cstddef>

#define T_LEN 512
#define BATCH 64
#define ISZ   256
#define HID   512
#define NCOL  2048      // 4*HID
#define GRID2 128       // 4 groups x 32 CTAs

// ---------------- device scratch ----------------
__device__ float g_gx[(size_t)T_LEN * NCOL * BATCH];   // [T][2048][64], bx+bh folded in
__device__ float g_h[2][BATCH * HID];                  // h double buffer
__device__ unsigned g_done[GRID2];                     // per-block step counters

// ---------------- packed fp32x2 FMA ----------------
__device__ __forceinline__ unsigned long long fma2(unsigned long long a,
                                                   unsigned long long b,
                                                   unsigned long long c) {
    unsigned long long d;
    asm("fma.rn.f32x2 %0, %1, %2, %3;" : "=l"(d) : "l"(a), "l"(b), "l"(c));
    return d;
}
__device__ __forceinline__ float hsum2(unsigned long long v) {
    float lo, hi;
    asm("mov.b64 {%0,%1}, %2;" : "=f"(lo), "=f"(hi) : "l"(v));
    return lo + hi;
}
__device__ __forceinline__ float sigf(float x) {
    return 1.0f / (1.0f + __expf(-x));
}
__device__ __forceinline__ float tanh_acc(float x) {
    float ax = fabsf(x);
    float e  = __expf(-2.0f * ax);
    float r  = (1.0f - e) / (1.0f + e);
    return copysignf(r, x);
}

// =====================================================================
// Phase 1 (proven): gx[t][n][b] = x[t,b,:]·Wx[n,:] + bx[n]+bh[n]
//   Also resets the phase-2 done slots (stream order guarantees safety).
// =====================================================================
#define P1_PAD 132

extern "C" __global__ void __launch_bounds__(256, 2)
lstm_phase1(const float* __restrict__ x, const float* __restrict__ Wx,
            const float* __restrict__ bx, const float* __restrict__ bh)
{
    extern __shared__ float smem[];
    float* xs   = smem;
    float* ws   = smem + 64 * P1_PAD;
    float* sbuf = smem;

    const int t   = blockIdx.y;
    const int n0  = blockIdx.x * 64;
    const int tid = threadIdx.x;
    const int nq  = tid & 15;
    const int bq  = tid >> 4;

    if (blockIdx.x == 0 && blockIdx.y == 0 && tid < GRID2) g_done[tid] = 0u;

    unsigned long long acc[4][4];
    #pragma unroll
    for (int a = 0; a < 4; a++)
        #pragma unroll
        for (int c = 0; c < 4; c++) acc[a][c] = 0ull;

    #pragma unroll
    for (int ks = 0; ks < 2; ks++) {
        const int k0 = ks * 128;
        __syncthreads();
        for (int e = tid; e < 64 * 32; e += 256) {
            int bb = e >> 5, kq = e & 31;
            float4 v = *reinterpret_cast<const float4*>(
                &x[((size_t)t * BATCH + bb) * ISZ + k0 + kq * 4]);
            *reinterpret_cast<float4*>(&xs[bb * P1_PAD + kq * 4]) = v;
        }
        for (int e = tid; e < 64 * 32; e += 256) {
            int r = e >> 5, kq = e & 31;
            float4 v = *reinterpret_cast<const float4*>(
                &Wx[(size_t)(n0 + r) * ISZ + k0 + kq * 4]);
            *reinterpret_cast<float4*>(&ws[r * P1_PAD + kq * 4]) = v;
        }
        __syncthreads();

        #pragma unroll 4
        for (int k4 = 0; k4 < 128; k4 += 4) {
            ulonglong2 xv[4], wv[4];
            #pragma unroll
            for (int rb = 0; rb < 4; rb++)
                xv[rb] = *reinterpret_cast<const ulonglong2*>(
                    &xs[(bq + 16 * rb) * P1_PAD + k4]);
            #pragma unroll
            for (int rn = 0; rn < 4; rn++)
                wv[rn] = *reinterpret_cast<const ulonglong2*>(
                    &ws[(nq + 16 * rn) * P1_PAD + k4]);
            #pragma unroll
            for (int rb = 0; rb < 4; rb++)
                #pragma unroll
                for (int rn = 0; rn < 4; rn++) {
                    acc[rb][rn] = fma2(xv[rb].x, wv[rn].x, acc[rb][rn]);
                    acc[rb][rn] = fma2(xv[rb].y, wv[rn].y, acc[rb][rn]);
                }
        }
    }
    __syncthreads();

    #pragma unroll
    for (int rb = 0; rb < 4; rb++)
        #pragma unroll
        for (int rn = 0; rn < 4; rn++)
            sbuf[(nq + 16 * rn) * 68 + (bq + 16 * rb)] = hsum2(acc[rb][rn]);
    __syncthreads();

    for (int e = tid; e < 64 * 16; e += 256) {
        int row = e >> 4, c4 = e & 15;
        int n = n0 + row;
        float bias = bx[n] + bh[n];
        float4 v = *reinterpret_cast<float4*>(&sbuf[row * 68 + c4 * 4]);
        v.x += bias; v.y += bias; v.z += bias; v.w += bias;
        *reinterpret_cast<float4*>(
            &g_gx[((size_t)t * NCOL + n) * BATCH + c4 * 4]) = v;
    }
}

// =====================================================================
// Phase 2: 4 independent groups x 32 CTAs (batch-parallel LSTM).
//   Group gr owns batches [gr*16, gr*16+16). CTA c-in-group owns units
//   [c*16, c*16+16) (64 gate-rows, Wh slice 132KB smem resident).
//   Per step a CTA stages only 16 rows x 512 k = 32KB of h (2048 cp.asyncs
//   vs 8192 before: the LSU-issue bottleneck found in R10's post-mortem).
//   thread = (kq 0..3, u 0..15, bb 0..7): 4 gates x 2 batches x 128 k.
//   kq-group (4 warps, one per SMSP) copies its own k-quarter -> own wait
//   -> named bar(128) -> dot. Barrier: 32 slots per group (proven protocol).
// =====================================================================
#define HS_PAD 516
#define WS_PAD 516
#define NTHR2  512

__device__ __forceinline__ void cpa_commit() {
    asm volatile("cp.async.commit_group;" ::: "memory");
}
template <int N>
__device__ __forceinline__ void cpa_wait() {
    asm volatile("cp.async.wait_group %0;" :: "n"(N) : "memory");
}

extern "C" __global__ void __launch_bounds__(NTHR2, 1)
lstm_phase2(const float* __restrict__ Wh, float* __restrict__ out)
{
    extern __shared__ float smem[];
    float* hs  = smem;                      // [16][516] h rows for this group's batches
    float* ws  = smem + 16 * HS_PAD;        // [64][516] Wh slice, row = g*16+u
    float* red = smem + 16 * HS_PAD + 64 * WS_PAD;  // [3][128][8]

    const int tid  = threadIdx.x;
    const int bid  = blockIdx.x;
    const int gr   = bid >> 5;              // group 0..3
    const int c    = bid & 31;              // CTA within group
    const int lane = tid & 31;
    const int kq   = tid >> 7;              // k-quarter 0..3
    const int r7   = tid & 127;
    const int u    = r7 >> 3;               // unit-in-CTA 0..15
    const int bb   = r7 & 7;                // batch pair: bb, bb+8 (local)
    const int j    = c * 16 + u;            // global unit
    const int b0   = gr * 16;               // group's first batch
    const int kofs = kq * 128;

    // Wh slice resident: ws[(g*16+u)][k] = Wh[g*512 + c*16 + u][k]
    for (int e = tid; e < 64 * 128; e += NTHR2) {
        int row = e >> 7, kk = e & 127;
        int g = row >> 4, uu = row & 15;
        float4 v = *reinterpret_cast<const float4*>(
            &Wh[((size_t)(g * HID + c * 16 + uu)) * HID + kk * 4]);
        *reinterpret_cast<float4*>(&ws[row * WS_PAD + kk * 4]) = v;
    }
    float c0 = 0.0f, c1 = 0.0f;
    __syncthreads();   // ws ready

    for (int t = 0; t < T_LEN; t++) {
        const int rb = t & 1;
        const int wbuf = rb ^ 1;

        // gx prefetch first — independent of h, hides LDG under the poll
        float gxa[4], gxb[4];
        if (kq == 0) {
            #pragma unroll
            for (int g = 0; g < 4; g++) {
                size_t base = ((size_t)t * NCOL + g * HID + j) * BATCH + b0;
                gxa[g] = g_gx[base + bb];
                gxb[g] = g_gx[base + bb + 8];
            }
        }

        unsigned long long accA[4] = {0ull, 0ull, 0ull, 0ull};
        unsigned long long accB[4] = {0ull, 0ull, 0ull, 0ull};

        if (t > 0) {
            // ---- group barrier wait: this group's 32 slots >= t ----
            if (tid < 32) {
                const unsigned need = (unsigned)t;
                bool ok;
                do {
                    unsigned v;
                    asm volatile("ld.relaxed.gpu.global.u32 %0, [%1];"
                                 : "=r"(v) : "l"(&g_done[(gr << 5) + lane]) : "memory");
                    ok = __all_sync(0xFFFFFFFFu, (int)(v - need) >= 0);
                    if (!ok) __nanosleep(20);
                } while (!ok);
                asm volatile("fence.acq_rel.gpu;" ::: "memory");
            }
            __syncthreads();   // everyone gated on h(t-1) ready

            // ---- kq-group copies ITS k-quarter: 16 rows x 128 floats ----
            const float* hsrc = g_h[rb] + (size_t)b0 * HID;
            {
                // 512 chunks of 16B per quarter; 128 threads x 4 chunks
                #pragma unroll
                for (int i = 0; i < 4; i++) {
                    int e  = r7 + i * 128;       // 0..511
                    int row = e >> 5;            // 0..15
                    int cc  = e & 31;            // 16B chunk in quarter
                    unsigned dst = (unsigned)__cvta_generic_to_shared(
                        &hs[row * HS_PAD + kofs + cc * 4]);
                    const float* src = &hsrc[(size_t)row * HID + kofs + cc * 4];
                    asm volatile("cp.async.cg.shared.global [%0], [%1], 16;"
                                 :: "r"(dst), "l"(src) : "memory");
                }
            }
            cpa_commit();
            cpa_wait<0>();
            asm volatile("bar.sync %0, 128;" :: "r"(1 + kq) : "memory");

            // ---- dot: 4 gates x 2 batches x 128 k ----
            const float* hr0 = &hs[bb * HS_PAD + kofs];
            const float* hr1 = &hs[(bb + 8) * HS_PAD + kofs];
            const float* w0 = &ws[(0 * 16 + u) * WS_PAD + kofs];
            const float* w1 = &ws[(1 * 16 + u) * WS_PAD + kofs];
            const float* w2 = &ws[(2 * 16 + u) * WS_PAD + kofs];
            const float* w3 = &ws[(3 * 16 + u) * WS_PAD + kofs];
            #pragma unroll 8
            for (int k4 = 0; k4 < 128; k4 += 4) {
                ulonglong2 ha = *reinterpret_cast<const ulonglong2*>(&hr0[k4]);
                ulonglong2 hb = *reinterpret_cast<const ulonglong2*>(&hr1[k4]);
                ulonglong2 wv0 = *reinterpret_cast<const ulonglong2*>(&w0[k4]);
                ulonglong2 wv1 = *reinterpret_cast<const ulonglong2*>(&w1[k4]);
                ulonglong2 wv2 = *reinterpret_cast<const ulonglong2*>(&w2[k4]);
                ulonglong2 wv3 = *reinterpret_cast<const ulonglong2*>(&w3[k4]);
                accA[0] = fma2(ha.x, wv0.x, accA[0]);
                accA[0] = fma2(ha.y, wv0.y, accA[0]);
                accB[0] = fma2(hb.x, wv0.x, accB[0]);
                accB[0] = fma2(hb.y, wv0.y, accB[0]);
                accA[1] = fma2(ha.x, wv1.x, accA[1]);
                accA[1] = fma2(ha.y, wv1.y, accA[1]);
                accB[1] = fma2(hb.x, wv1.x, accB[1]);
                accB[1] = fma2(hb.y, wv1.y, accB[1]);
                accA[2] = fma2(ha.x, wv2.x, accA[2]);
                accA[2] = fma2(ha.y, wv2.y, accA[2]);
                accB[2] = fma2(hb.x, wv2.x, accB[2]);
                accB[2] = fma2(hb.y, wv2.y, accB[2]);
                accA[3] = fma2(ha.x, wv3.x, accA[3]);
                accA[3] = fma2(ha.y, wv3.y, accA[3]);
                accB[3] = fma2(hb.x, wv3.x, accB[3]);
                accB[3] = fma2(hb.y, wv3.y, accB[3]);
            }
        }

        float pa[4], pb[4];
        #pragma unroll
        for (int g = 0; g < 4; g++) { pa[g] = hsum2(accA[g]); pb[g] = hsum2(accB[g]); }

        if (kq != 0) {
            float* rs = &red[((kq - 1) * 128 + r7) * 8];
            *reinterpret_cast<float4*>(rs)     = make_float4(pa[0], pa[1], pa[2], pa[3]);
            *reinterpret_cast<float4*>(rs + 4) = make_float4(pb[0], pb[1], pb[2], pb[3]);
        }
        __syncthreads();   // partials visible

        float h0 = 0.f, h1 = 0.f;
        if (kq == 0) {
            #pragma unroll
            for (int q = 0; q < 3; q++) {
                const float* rs = &red[(q * 128 + r7) * 8];
                float4 va = *reinterpret_cast<const float4*>(rs);
                float4 vb = *reinterpret_cast<const float4*>(rs + 4);
                pa[0] += va.x; pa[1] += va.y; pa[2] += va.z; pa[3] += va.w;
                pb[0] += vb.x; pb[1] += vb.y; pb[2] += vb.z; pb[3] += vb.w;
            }
            {
                float f  = sigf(pa[0] + gxa[0]);
                float i  = sigf(pa[1] + gxa[1]);
                float o  = sigf(pa[2] + gxa[2]);
                float cc = tanh_acc(pa[3] + gxa[3]);
                c0 = f * c0 + i * cc;
                h0 = o * tanh_acc(c0);
            }
            {
                float f  = sigf(pb[0] + gxb[0]);
                float i  = sigf(pb[1] + gxb[1]);
                float o  = sigf(pb[2] + gxb[2]);
                float cc = tanh_acc(pb[3] + gxb[3]);
                c1 = f * c1 + i * cc;
                h1 = o * tanh_acc(c1);
            }
            g_h[wbuf][(size_t)(b0 + bb) * HID + j]     = h0;
            g_h[wbuf][(size_t)(b0 + bb + 8) * HID + j] = h1;
            __threadfence();   // drains only the two g_h stores
        }
        __syncthreads();       // all h(t) stores done block-wide

        if (tid == 0) {
            __threadfence();   // cumulativity: block's stores before release
            asm volatile("st.release.gpu.global.u32 [%0], %1;"
                         :: "l"(&g_done[bid]), "r"((unsigned)(t + 1)) : "memory");
        }

        // out stores AFTER release — off the recurrence critical path
        if (kq == 0) {
            out[((size_t)t * BATCH + b0 + bb) * HID + j]     = h0;
            out[((size_t)t * BATCH + b0 + bb + 8) * HID + j] = h1;
            if (t == T_LEN - 1) {
                size_t ofs = (size_t)T_LEN * BATCH * HID;
                out[ofs + (size_t)(b0 + bb) * HID + j]     = h0;
                out[ofs + (size_t)(b0 + bb + 8) * HID + j] = h1;
                ofs += (size_t)BATCH * HID;
                out[ofs + (size_t)(b0 + bb) * HID + j]     = c0;
                out[ofs + (size_t)(b0 + bb + 8) * HID + j] = c1;
            }
        }
        // next iteration's poll+syncthreads gates all cross-step reads
    }
}

// =====================================================================
// launch
// =====================================================================
extern "C" void kernel_launch(void* const* d_in, const int* in_sizes, int n_in,
                              void* d_out, int out_size) {
    (void)in_sizes; (void)n_in; (void)out_size;
    const float* x  = (const float*)d_in[0];
    const float* Wx = (const float*)d_in[1];
    const float* bx = (const float*)d_in[2];
    const float* Wh = (const float*)d_in[3];
    const float* bh = (const float*)d_in[4];
    float* out = (float*)d_out;

    const int smem1 = 2 * 64 * P1_PAD * sizeof(float);
    const int smem2 = (16 * HS_PAD + 64 * WS_PAD + 3 * 128 * 8) * sizeof(float);
    cudaFuncSetAttribute(lstm_phase1, cudaFuncAttributeMaxDynamicSharedMemorySize, smem1);
    cudaFuncSetAttribute(lstm_phase2, cudaFuncAttributeMaxDynamicSharedMemorySize, smem2);

    dim3 g1(32, T_LEN);
    lstm_phase1<<<g1, 256, smem1>>>(x, Wx, bx, bh);
    lstm_phase2<<<GRID2, NTHR2, smem2>>>(Wh, out);
}

// round 12
// speedup vs baseline: 1.6257x; 1.1195x over previous
#include <cuda_runtime.h>
#include <cstdint>
#include <cstddef>

#define T_LEN 512
#define BATCH 64
#define ISZ   256
#define HID   512
#define NCOL  2048      // 4*HID
#define GRID2 128       // 4 groups x 32 CTAs

// ---------------- device scratch ----------------
__device__ float g_gx[(size_t)T_LEN * NCOL * BATCH];   // [T][2048][64], bx+bh folded in
__device__ float g_h[2][BATCH * HID];                  // h double buffer
__device__ unsigned g_done[GRID2];                     // per-block step counters

// ---------------- packed fp32x2 FMA ----------------
__device__ __forceinline__ unsigned long long fma2(unsigned long long a,
                                                   unsigned long long b,
                                                   unsigned long long c) {
    unsigned long long d;
    asm("fma.rn.f32x2 %0, %1, %2, %3;" : "=l"(d) : "l"(a), "l"(b), "l"(c));
    return d;
}
__device__ __forceinline__ float hsum2(unsigned long long v) {
    float lo, hi;
    asm("mov.b64 {%0,%1}, %2;" : "=f"(lo), "=f"(hi) : "l"(v));
    return lo + hi;
}
__device__ __forceinline__ float sigf(float x) {
    return 1.0f / (1.0f + __expf(-x));
}
__device__ __forceinline__ float tanh_acc(float x) {
    float ax = fabsf(x);
    float e  = __expf(-2.0f * ax);
    float r  = (1.0f - e) / (1.0f + e);
    return copysignf(r, x);
}

// =====================================================================
// Phase 1 (proven): gx[t][n][b] = x[t,b,:]·Wx[n,:] + bx[n]+bh[n]
//   Also resets the phase-2 done slots (stream order guarantees safety).
// =====================================================================
#define P1_PAD 132

extern "C" __global__ void __launch_bounds__(256, 2)
lstm_phase1(const float* __restrict__ x, const float* __restrict__ Wx,
            const float* __restrict__ bx, const float* __restrict__ bh)
{
    extern __shared__ float smem[];
    float* xs   = smem;
    float* ws   = smem + 64 * P1_PAD;
    float* sbuf = smem;

    const int t   = blockIdx.y;
    const int n0  = blockIdx.x * 64;
    const int tid = threadIdx.x;
    const int nq  = tid & 15;
    const int bq  = tid >> 4;

    if (blockIdx.x == 0 && blockIdx.y == 0 && tid < GRID2) g_done[tid] = 0u;

    unsigned long long acc[4][4];
    #pragma unroll
    for (int a = 0; a < 4; a++)
        #pragma unroll
        for (int c = 0; c < 4; c++) acc[a][c] = 0ull;

    #pragma unroll
    for (int ks = 0; ks < 2; ks++) {
        const int k0 = ks * 128;
        __syncthreads();
        for (int e = tid; e < 64 * 32; e += 256) {
            int bb = e >> 5, kq = e & 31;
            float4 v = *reinterpret_cast<const float4*>(
                &x[((size_t)t * BATCH + bb) * ISZ + k0 + kq * 4]);
            *reinterpret_cast<float4*>(&xs[bb * P1_PAD + kq * 4]) = v;
        }
        for (int e = tid; e < 64 * 32; e += 256) {
            int r = e >> 5, kq = e & 31;
            float4 v = *reinterpret_cast<const float4*>(
                &Wx[(size_t)(n0 + r) * ISZ + k0 + kq * 4]);
            *reinterpret_cast<float4*>(&ws[r * P1_PAD + kq * 4]) = v;
        }
        __syncthreads();

        #pragma unroll 4
        for (int k4 = 0; k4 < 128; k4 += 4) {
            ulonglong2 xv[4], wv[4];
            #pragma unroll
            for (int rb = 0; rb < 4; rb++)
                xv[rb] = *reinterpret_cast<const ulonglong2*>(
                    &xs[(bq + 16 * rb) * P1_PAD + k4]);
            #pragma unroll
            for (int rn = 0; rn < 4; rn++)
                wv[rn] = *reinterpret_cast<const ulonglong2*>(
                    &ws[(nq + 16 * rn) * P1_PAD + k4]);
            #pragma unroll
            for (int rb = 0; rb < 4; rb++)
                #pragma unroll
                for (int rn = 0; rn < 4; rn++) {
                    acc[rb][rn] = fma2(xv[rb].x, wv[rn].x, acc[rb][rn]);
                    acc[rb][rn] = fma2(xv[rb].y, wv[rn].y, acc[rb][rn]);
                }
        }
    }
    __syncthreads();

    #pragma unroll
    for (int rb = 0; rb < 4; rb++)
        #pragma unroll
        for (int rn = 0; rn < 4; rn++)
            sbuf[(nq + 16 * rn) * 68 + (bq + 16 * rb)] = hsum2(acc[rb][rn]);
    __syncthreads();

    for (int e = tid; e < 64 * 16; e += 256) {
        int row = e >> 4, c4 = e & 15;
        int n = n0 + row;
        float bias = bx[n] + bh[n];
        float4 v = *reinterpret_cast<float4*>(&sbuf[row * 68 + c4 * 4]);
        v.x += bias; v.y += bias; v.z += bias; v.w += bias;
        *reinterpret_cast<float4*>(
            &g_gx[((size_t)t * NCOL + n) * BATCH + c4 * 4]) = v;
    }
}

// =====================================================================
// Phase 2: 4 independent groups x 32 CTAs (batch-parallel LSTM).
//   Identical protocol to R11 (proven) EXCEPT h staging: 16 cp.async.bulk
//   (2KB/row) + mbarrier replace 2048 per-thread cp.asyncs, removing
//   ~4096 cyc/SMSP of LSU issue from the per-step critical path.
// =====================================================================
#define HS_PAD 516
#define WS_PAD 516
#define NTHR2  512
#define H_ROW_BYTES (HID * 4)          // 2048
#define H_TILE_BYTES (16 * H_ROW_BYTES)  // 32768

extern "C" __global__ void __launch_bounds__(NTHR2, 1)
lstm_phase2(const float* __restrict__ Wh, float* __restrict__ out)
{
    extern __shared__ float smem[];
    float* hs  = smem;                      // [16][516] h rows for this group's batches
    float* ws  = smem + 16 * HS_PAD;        // [64][516] Wh slice, row = g*16+u
    float* red = smem + 16 * HS_PAD + 64 * WS_PAD;  // [3][128][8]
    __shared__ unsigned long long s_mbar;   // bulk-copy completion barrier

    const int tid  = threadIdx.x;
    const int bid  = blockIdx.x;
    const int gr   = bid >> 5;              // group 0..3
    const int c    = bid & 31;              // CTA within group
    const int lane = tid & 31;
    const int kq   = tid >> 7;              // k-quarter 0..3
    const int r7   = tid & 127;
    const int u    = r7 >> 3;               // unit-in-CTA 0..15
    const int bb   = r7 & 7;                // batch pair: bb, bb+8 (local)
    const int j    = c * 16 + u;            // global unit
    const int b0   = gr * 16;               // group's first batch
    const int kofs = kq * 128;

    uint32_t mbar_addr;
    {
        uint64_t tmp;
        asm("cvta.to.shared.u64 %0, %1;" : "=l"(tmp) : "l"(&s_mbar));
        mbar_addr = (uint32_t)tmp;
    }

    // Wh slice resident: ws[(g*16+u)][k] = Wh[g*512 + c*16 + u][k]
    for (int e = tid; e < 64 * 128; e += NTHR2) {
        int row = e >> 7, kk = e & 127;
        int g = row >> 4, uu = row & 15;
        float4 v = *reinterpret_cast<const float4*>(
            &Wh[((size_t)(g * HID + c * 16 + uu)) * HID + kk * 4]);
        *reinterpret_cast<float4*>(&ws[row * WS_PAD + kk * 4]) = v;
    }
    if (tid == 0) {
        asm volatile("mbarrier.init.shared.b64 [%0], 1;"
                     :: "r"(mbar_addr) : "memory");
    }
    float c0 = 0.0f, c1 = 0.0f;
    unsigned ph = 0;                        // mbarrier phase parity
    __syncthreads();   // ws + mbar ready

    for (int t = 0; t < T_LEN; t++) {
        const int rb = t & 1;
        const int wbuf = rb ^ 1;

        // gx prefetch first — independent of h, hides LDG under the poll
        float gxa[4], gxb[4];
        if (kq == 0) {
            #pragma unroll
            for (int g = 0; g < 4; g++) {
                size_t base = ((size_t)t * NCOL + g * HID + j) * BATCH + b0;
                gxa[g] = g_gx[base + bb];
                gxb[g] = g_gx[base + bb + 8];
            }
        }

        unsigned long long accA[4] = {0ull, 0ull, 0ull, 0ull};
        unsigned long long accB[4] = {0ull, 0ull, 0ull, 0ull};

        if (t > 0) {
            // ---- group barrier wait: this group's 32 slots >= t ----
            if (tid < 32) {
                const unsigned need = (unsigned)t;
                bool ok;
                do {
                    unsigned v;
                    asm volatile("ld.relaxed.gpu.global.u32 %0, [%1];"
                                 : "=r"(v) : "l"(&g_done[(gr << 5) + lane]) : "memory");
                    ok = __all_sync(0xFFFFFFFFu, (int)(v - need) >= 0);
                    if (!ok) __nanosleep(20);
                } while (!ok);
                asm volatile("fence.acq_rel.gpu;" ::: "memory");
            }
            __syncthreads();   // everyone gated on h(t-1) ready; hs WAR-safe

            // ---- bulk-copy 16 h rows (2KB each) via async proxy ----
            if (tid == 0) {
                asm volatile("mbarrier.arrive.expect_tx.shared.b64 _, [%0], %1;"
                             :: "r"(mbar_addr), "r"((unsigned)H_TILE_BYTES)
                             : "memory");
                const float* hsrc = g_h[rb] + (size_t)b0 * HID;
                #pragma unroll
                for (int r = 0; r < 16; r++) {
                    uint32_t dst;
                    {
                        uint64_t tmp;
                        asm("cvta.to.shared.u64 %0, %1;"
                            : "=l"(tmp) : "l"(&hs[r * HS_PAD]));
                        dst = (uint32_t)tmp;
                    }
                    asm volatile(
                        "cp.async.bulk.shared::cta.global.mbarrier::complete_tx::bytes"
                        " [%0], [%1], %2, [%3];"
                        :: "r"(dst), "l"(&hsrc[(size_t)r * HID]),
                           "r"((unsigned)H_ROW_BYTES), "r"(mbar_addr)
                        : "memory");
                }
            }
            // wait for all 32KB to land (async-proxy visibility included)
            {
                unsigned done;
                asm volatile(
                    "{\n\t.reg .pred p;\n\t"
                    "mbarrier.try_wait.parity.shared.b64 p, [%1], %2;\n\t"
                    "selp.b32 %0, 1, 0, p;\n\t}"
                    : "=r"(done) : "r"(mbar_addr), "r"(ph) : "memory");
                while (!done) {
                    asm volatile(
                        "{\n\t.reg .pred p;\n\t"
                        "mbarrier.try_wait.parity.shared.b64 p, [%1], %2;\n\t"
                        "selp.b32 %0, 1, 0, p;\n\t}"
                        : "=r"(done) : "r"(mbar_addr), "r"(ph) : "memory");
                }
            }
            ph ^= 1u;

            // ---- dot: 4 gates x 2 batches x 128 k ----
            const float* hr0 = &hs[bb * HS_PAD + kofs];
            const float* hr1 = &hs[(bb + 8) * HS_PAD + kofs];
            const float* w0 = &ws[(0 * 16 + u) * WS_PAD + kofs];
            const float* w1 = &ws[(1 * 16 + u) * WS_PAD + kofs];
            const float* w2 = &ws[(2 * 16 + u) * WS_PAD + kofs];
            const float* w3 = &ws[(3 * 16 + u) * WS_PAD + kofs];
            #pragma unroll 8
            for (int k4 = 0; k4 < 128; k4 += 4) {
                ulonglong2 ha = *reinterpret_cast<const ulonglong2*>(&hr0[k4]);
                ulonglong2 hb = *reinterpret_cast<const ulonglong2*>(&hr1[k4]);
                ulonglong2 wv0 = *reinterpret_cast<const ulonglong2*>(&w0[k4]);
                ulonglong2 wv1 = *reinterpret_cast<const ulonglong2*>(&w1[k4]);
                ulonglong2 wv2 = *reinterpret_cast<const ulonglong2*>(&w2[k4]);
                ulonglong2 wv3 = *reinterpret_cast<const ulonglong2*>(&w3[k4]);
                accA[0] = fma2(ha.x, wv0.x, accA[0]);
                accA[0] = fma2(ha.y, wv0.y, accA[0]);
                accB[0] = fma2(hb.x, wv0.x, accB[0]);
                accB[0] = fma2(hb.y, wv0.y, accB[0]);
                accA[1] = fma2(ha.x, wv1.x, accA[1]);
                accA[1] = fma2(ha.y, wv1.y, accA[1]);
                accB[1] = fma2(hb.x, wv1.x, accB[1]);
                accB[1] = fma2(hb.y, wv1.y, accB[1]);
                accA[2] = fma2(ha.x, wv2.x, accA[2]);
                accA[2] = fma2(ha.y, wv2.y, accA[2]);
                accB[2] = fma2(hb.x, wv2.x, accB[2]);
                accB[2] = fma2(hb.y, wv2.y, accB[2]);
                accA[3] = fma2(ha.x, wv3.x, accA[3]);
                accA[3] = fma2(ha.y, wv3.y, accA[3]);
                accB[3] = fma2(hb.x, wv3.x, accB[3]);
                accB[3] = fma2(hb.y, wv3.y, accB[3]);
            }
        }

        float pa[4], pb[4];
        #pragma unroll
        for (int g = 0; g < 4; g++) { pa[g] = hsum2(accA[g]); pb[g] = hsum2(accB[g]); }

        if (kq != 0) {
            float* rs = &red[((kq - 1) * 128 + r7) * 8];
            *reinterpret_cast<float4*>(rs)     = make_float4(pa[0], pa[1], pa[2], pa[3]);
            *reinterpret_cast<float4*>(rs + 4) = make_float4(pb[0], pb[1], pb[2], pb[3]);
        }
        __syncthreads();   // partials visible; all hs reads complete

        float h0 = 0.f, h1 = 0.f;
        if (kq == 0) {
            #pragma unroll
            for (int q = 0; q < 3; q++) {
                const float* rs = &red[(q * 128 + r7) * 8];
                float4 va = *reinterpret_cast<const float4*>(rs);
                float4 vb = *reinterpret_cast<const float4*>(rs + 4);
                pa[0] += va.x; pa[1] += va.y; pa[2] += va.z; pa[3] += va.w;
                pb[0] += vb.x; pb[1] += vb.y; pb[2] += vb.z; pb[3] += vb.w;
            }
            {
                float f  = sigf(pa[0] + gxa[0]);
                float i  = sigf(pa[1] + gxa[1]);
                float o  = sigf(pa[2] + gxa[2]);
                float cc = tanh_acc(pa[3] + gxa[3]);
                c0 = f * c0 + i * cc;
                h0 = o * tanh_acc(c0);
            }
            {
                float f  = sigf(pb[0] + gxb[0]);
                float i  = sigf(pb[1] + gxb[1]);
                float o  = sigf(pb[2] + gxb[2]);
                float cc = tanh_acc(pb[3] + gxb[3]);
                c1 = f * c1 + i * cc;
                h1 = o * tanh_acc(c1);
            }
            g_h[wbuf][(size_t)(b0 + bb) * HID + j]     = h0;
            g_h[wbuf][(size_t)(b0 + bb + 8) * HID + j] = h1;
            __threadfence();   // drains only the two g_h stores
        }
        __syncthreads();       // all h(t) stores done block-wide

        if (tid == 0) {
            __threadfence();   // cumulativity: block's stores before release
            asm volatile("st.release.gpu.global.u32 [%0], %1;"
                         :: "l"(&g_done[bid]), "r"((unsigned)(t + 1)) : "memory");
        }

        // out stores AFTER release — off the recurrence critical path
        if (kq == 0) {
            out[((size_t)t * BATCH + b0 + bb) * HID + j]     = h0;
            out[((size_t)t * BATCH + b0 + bb + 8) * HID + j] = h1;
            if (t == T_LEN - 1) {
                size_t ofs = (size_t)T_LEN * BATCH * HID;
                out[ofs + (size_t)(b0 + bb) * HID + j]     = h0;
                out[ofs + (size_t)(b0 + bb + 8) * HID + j] = h1;
                ofs += (size_t)BATCH * HID;
                out[ofs + (size_t)(b0 + bb) * HID + j]     = c0;
                out[ofs + (size_t)(b0 + bb + 8) * HID + j] = c1;
            }
        }
        // next iteration's poll+syncthreads gates all cross-step reads
    }
}

// =====================================================================
// launch
// =====================================================================
extern "C" void kernel_launch(void* const* d_in, const int* in_sizes, int n_in,
                              void* d_out, int out_size) {
    (void)in_sizes; (void)n_in; (void)out_size;
    const float* x  = (const float*)d_in[0];
    const float* Wx = (const float*)d_in[1];
    const float* bx = (const float*)d_in[2];
    const float* Wh = (const float*)d_in[3];
    const float* bh = (const float*)d_in[4];
    float* out = (float*)d_out;

    const int smem1 = 2 * 64 * P1_PAD * sizeof(float);
    const int smem2 = (16 * HS_PAD + 64 * WS_PAD + 3 * 128 * 8) * sizeof(float);
    cudaFuncSetAttribute(lstm_phase1, cudaFuncAttributeMaxDynamicSharedMemorySize, smem1);
    cudaFuncSetAttribute(lstm_phase2, cudaFuncAttributeMaxDynamicSharedMemorySize, smem2);

    dim3 g1(32, T_LEN);
    lstm_phase1<<<g1, 256, smem1>>>(x, Wx, bx, bh);
    lstm_phase2<<<GRID2, NTHR2, smem2>>>(Wh, out);
}

// round 14
// speedup vs baseline: 1.9194x; 1.1806x over previous
#include <cuda_runtime.h>
#include <cstdint>
#include <cstddef>

#define T_LEN 512
#define BATCH 64
#define ISZ   256
#define HID   512
#define NCOL  2048      // 4*HID
#define GRID2 128       // 4 groups x 32 CTAs

// ---------------- device scratch ----------------
__device__ float g_gx[(size_t)T_LEN * NCOL * BATCH];   // [T][2048][64], bx+bh folded in
__device__ float g_h[2][BATCH * HID];                  // h double buffer
__device__ unsigned g_done[GRID2];                     // per-block step counters

// ---------------- packed fp32x2 FMA ----------------
__device__ __forceinline__ unsigned long long fma2(unsigned long long a,
                                                   unsigned long long b,
                                                   unsigned long long c) {
    unsigned long long d;
    asm("fma.rn.f32x2 %0, %1, %2, %3;" : "=l"(d) : "l"(a), "l"(b), "l"(c));
    return d;
}
__device__ __forceinline__ float hsum2(unsigned long long v) {
    float lo, hi;
    asm("mov.b64 {%0,%1}, %2;" : "=f"(lo), "=f"(hi) : "l"(v));
    return lo + hi;
}
__device__ __forceinline__ float sigf(float x) {
    return 1.0f / (1.0f + __expf(-x));
}
__device__ __forceinline__ float tanh_acc(float x) {
    float ax = fabsf(x);
    float e  = __expf(-2.0f * ax);
    float r  = (1.0f - e) / (1.0f + e);
    return copysignf(r, x);
}

// =====================================================================
// Phase 1 (proven): gx[t][n][b] = x[t,b,:]·Wx[n,:] + bx[n]+bh[n]
//   Also resets the phase-2 done slots (stream order guarantees safety).
// =====================================================================
#define P1_PAD 132

extern "C" __global__ void __launch_bounds__(256, 2)
lstm_phase1(const float* __restrict__ x, const float* __restrict__ Wx,
            const float* __restrict__ bx, const float* __restrict__ bh)
{
    extern __shared__ float smem[];
    float* xs   = smem;
    float* ws   = smem + 64 * P1_PAD;
    float* sbuf = smem;

    const int t   = blockIdx.y;
    const int n0  = blockIdx.x * 64;
    const int tid = threadIdx.x;
    const int nq  = tid & 15;
    const int bq  = tid >> 4;

    if (blockIdx.x == 0 && blockIdx.y == 0 && tid < GRID2) g_done[tid] = 0u;

    unsigned long long acc[4][4];
    #pragma unroll
    for (int a = 0; a < 4; a++)
        #pragma unroll
        for (int c = 0; c < 4; c++) acc[a][c] = 0ull;

    #pragma unroll
    for (int ks = 0; ks < 2; ks++) {
        const int k0 = ks * 128;
        __syncthreads();
        for (int e = tid; e < 64 * 32; e += 256) {
            int bb = e >> 5, kq = e & 31;
            float4 v = *reinterpret_cast<const float4*>(
                &x[((size_t)t * BATCH + bb) * ISZ + k0 + kq * 4]);
            *reinterpret_cast<float4*>(&xs[bb * P1_PAD + kq * 4]) = v;
        }
        for (int e = tid; e < 64 * 32; e += 256) {
            int r = e >> 5, kq = e & 31;
            float4 v = *reinterpret_cast<const float4*>(
                &Wx[(size_t)(n0 + r) * ISZ + k0 + kq * 4]);
            *reinterpret_cast<float4*>(&ws[r * P1_PAD + kq * 4]) = v;
        }
        __syncthreads();

        #pragma unroll 4
        for (int k4 = 0; k4 < 128; k4 += 4) {
            ulonglong2 xv[4], wv[4];
            #pragma unroll
            for (int rb = 0; rb < 4; rb++)
                xv[rb] = *reinterpret_cast<const ulonglong2*>(
                    &xs[(bq + 16 * rb) * P1_PAD + k4]);
            #pragma unroll
            for (int rn = 0; rn < 4; rn++)
                wv[rn] = *reinterpret_cast<const ulonglong2*>(
                    &ws[(nq + 16 * rn) * P1_PAD + k4]);
            #pragma unroll
            for (int rb = 0; rb < 4; rb++)
                #pragma unroll
                for (int rn = 0; rn < 4; rn++) {
                    acc[rb][rn] = fma2(xv[rb].x, wv[rn].x, acc[rb][rn]);
                    acc[rb][rn] = fma2(xv[rb].y, wv[rn].y, acc[rb][rn]);
                }
        }
    }
    __syncthreads();

    #pragma unroll
    for (int rb = 0; rb < 4; rb++)
        #pragma unroll
        for (int rn = 0; rn < 4; rn++)
            sbuf[(nq + 16 * rn) * 68 + (bq + 16 * rb)] = hsum2(acc[rb][rn]);
    __syncthreads();

    for (int e = tid; e < 64 * 16; e += 256) {
        int row = e >> 4, c4 = e & 15;
        int n = n0 + row;
        float bias = bx[n] + bh[n];
        float4 v = *reinterpret_cast<float4*>(&sbuf[row * 68 + c4 * 4]);
        v.x += bias; v.y += bias; v.z += bias; v.w += bias;
        *reinterpret_cast<float4*>(
            &g_gx[((size_t)t * NCOL + n) * BATCH + c4 * 4]) = v;
    }
}

// =====================================================================
// Phase 2: 4 groups x 32 CTAs, protocol identical to R12 (proven).
//   NEW dot tiling (LDS-minimizing): 256 threads,
//   thread = (ks 0..7 | bq 0..1 | u 0..15):
//     dot: 4 gates x 8 batches (b = bq + 2i) over k in [ks*64, ks*64+64)
//     warp = 16 u -> w-loads 16-wide broadcast; h-loads 2 rows on distinct banks
//   Every thread finalizes ONE (batch bf = 2*ks+bq, unit j): reduction via
//   padded red[], gate math parallel across all 256 threads.
// =====================================================================
#define HS_PAD 516
#define WS_PAD 516
#define RED_PAD 9      // per-(b,u) ks-stride in float4 units (avoids 128B alias)
#define NTHR2  256
#define H_ROW_BYTES (HID * 4)            // 2048
#define H_TILE_BYTES (16 * H_ROW_BYTES)  // 32768

extern "C" __global__ void __launch_bounds__(NTHR2, 1)
lstm_phase2(const float* __restrict__ Wh, float* __restrict__ out)
{
    extern __shared__ float smem[];
    float* hs  = smem;                      // [16][516] h rows (group's batches)
    float* ws  = smem + 16 * HS_PAD;        // [64][516] Wh slice, row = g*16+u
    float* red = smem + 16 * HS_PAD + 64 * WS_PAD;  // [16][16][RED_PAD] float4
    __shared__ unsigned long long s_mbar;

    const int tid  = threadIdx.x;
    const int bid  = blockIdx.x;
    const int gr   = bid >> 5;              // group 0..3
    const int c    = bid & 31;              // CTA within group
    const int lane = tid & 31;
    const int ks   = tid >> 5;              // k-slice 0..7 (64 k each)
    const int bq   = (tid >> 4) & 1;        // batch parity
    const int u    = tid & 15;              // unit-in-CTA
    const int j    = c * 16 + u;            // global unit
    const int b0   = gr * 16;               // group's first batch
    const int kofs = ks * 64;
    const int bf   = 2 * ks + bq;           // the one batch this thread finalizes

    uint32_t mbar_addr;
    {
        uint64_t tmp;
        asm("cvta.to.shared.u64 %0, %1;" : "=l"(tmp) : "l"(&s_mbar));
        mbar_addr = (uint32_t)tmp;
    }

    // Wh slice resident: ws[(g*16+uu)][k] = Wh[g*512 + c*16 + uu][k]
    for (int e = tid; e < 64 * 128; e += NTHR2) {
        int row = e >> 7, kk = e & 127;
        int g = row >> 4, uu = row & 15;
        float4 v = *reinterpret_cast<const float4*>(
            &Wh[((size_t)(g * HID + c * 16 + uu)) * HID + kk * 4]);
        *reinterpret_cast<float4*>(&ws[row * WS_PAD + kk * 4]) = v;
    }
    if (tid == 0) {
        asm volatile("mbarrier.init.shared.b64 [%0], 1;"
                     :: "r"(mbar_addr) : "memory");
    }
    float c_state = 0.0f;
    unsigned ph = 0;
    __syncthreads();   // ws + mbar ready

    for (int t = 0; t < T_LEN; t++) {
        const int rb = t & 1;
        const int wbuf = rb ^ 1;

        // gx prefetch (every thread finalizes one (bf, j)) — hides LDG under poll
        float gxv[4];
        #pragma unroll
        for (int g = 0; g < 4; g++)
            gxv[g] = g_gx[((size_t)t * NCOL + g * HID + j) * BATCH + b0 + bf];

        unsigned long long acc[4][8];
        #pragma unroll
        for (int g = 0; g < 4; g++)
            #pragma unroll
            for (int i = 0; i < 8; i++) acc[g][i] = 0ull;

        if (t > 0) {
            // ---- group barrier wait: this group's 32 slots >= t ----
            if (tid < 32) {
                const unsigned need = (unsigned)t;
                bool ok;
                do {
                    unsigned v;
                    asm volatile("ld.relaxed.gpu.global.u32 %0, [%1];"
                                 : "=r"(v) : "l"(&g_done[(gr << 5) + lane]) : "memory");
                    ok = __all_sync(0xFFFFFFFFu, (int)(v - need) >= 0);
                    if (!ok) __nanosleep(20);
                } while (!ok);
                asm volatile("fence.acq_rel.gpu;" ::: "memory");
            }
            __syncthreads();   // gated on h(t-1) ready; hs WAR-safe

            // ---- bulk-copy 16 h rows (2KB each) via async proxy ----
            if (tid == 0) {
                asm volatile("mbarrier.arrive.expect_tx.shared.b64 _, [%0], %1;"
                             :: "r"(mbar_addr), "r"((unsigned)H_TILE_BYTES)
                             : "memory");
                const float* hsrc = g_h[rb] + (size_t)b0 * HID;
                #pragma unroll
                for (int r = 0; r < 16; r++) {
                    uint32_t dst;
                    {
                        uint64_t tmp;
                        asm("cvta.to.shared.u64 %0, %1;"
                            : "=l"(tmp) : "l"(&hs[r * HS_PAD]));
                        dst = (uint32_t)tmp;
                    }
                    asm volatile(
                        "cp.async.bulk.shared::cta.global.mbarrier::complete_tx::bytes"
                        " [%0], [%1], %2, [%3];"
                        :: "r"(dst), "l"(&hsrc[(size_t)r * HID]),
                           "r"((unsigned)H_ROW_BYTES), "r"(mbar_addr)
                        : "memory");
                }
            }
            {
                unsigned done;
                asm volatile(
                    "{\n\t.reg .pred p;\n\t"
                    "mbarrier.try_wait.parity.shared.b64 p, [%1], %2;\n\t"
                    "selp.b32 %0, 1, 0, p;\n\t}"
                    : "=r"(done) : "r"(mbar_addr), "r"(ph) : "memory");
                while (!done) {
                    asm volatile(
                        "{\n\t.reg .pred p;\n\t"
                        "mbarrier.try_wait.parity.shared.b64 p, [%1], %2;\n\t"
                        "selp.b32 %0, 1, 0, p;\n\t}"
                        : "=r"(done) : "r"(mbar_addr), "r"(ph) : "memory");
                }
            }
            ph ^= 1u;

            // ---- dot: 4 gates x 8 batches (b = bq+2i) over 64 k ----
            const float* wp0 = &ws[(0 * 16 + u) * WS_PAD + kofs];
            const float* wp1 = &ws[(1 * 16 + u) * WS_PAD + kofs];
            const float* wp2 = &ws[(2 * 16 + u) * WS_PAD + kofs];
            const float* wp3 = &ws[(3 * 16 + u) * WS_PAD + kofs];
            const float* hp  = &hs[bq * HS_PAD + kofs];
            #pragma unroll 4
            for (int k4 = 0; k4 < 64; k4 += 4) {
                ulonglong2 w0 = *reinterpret_cast<const ulonglong2*>(&wp0[k4]);
                ulonglong2 w1 = *reinterpret_cast<const ulonglong2*>(&wp1[k4]);
                ulonglong2 w2 = *reinterpret_cast<const ulonglong2*>(&wp2[k4]);
                ulonglong2 w3 = *reinterpret_cast<const ulonglong2*>(&wp3[k4]);
                #pragma unroll
                for (int i = 0; i < 8; i++) {
                    ulonglong2 h2 = *reinterpret_cast<const ulonglong2*>(
                        &hp[(2 * i) * HS_PAD + k4]);
                    acc[0][i] = fma2(h2.x, w0.x, acc[0][i]);
                    acc[0][i] = fma2(h2.y, w0.y, acc[0][i]);
                    acc[1][i] = fma2(h2.x, w1.x, acc[1][i]);
                    acc[1][i] = fma2(h2.y, w1.y, acc[1][i]);
                    acc[2][i] = fma2(h2.x, w2.x, acc[2][i]);
                    acc[2][i] = fma2(h2.y, w2.y, acc[2][i]);
                    acc[3][i] = fma2(h2.x, w3.x, acc[3][i]);
                    acc[3][i] = fma2(h2.y, w3.y, acc[3][i]);
                }
            }
        }

        // write partials for all 8 batches this thread computed
        #pragma unroll
        for (int i = 0; i < 8; i++) {
            int b = bq + 2 * i;
            float4 pv = make_float4(hsum2(acc[0][i]), hsum2(acc[1][i]),
                                    hsum2(acc[2][i]), hsum2(acc[3][i]));
            *reinterpret_cast<float4*>(
                &red[((b * 16 + u) * RED_PAD + ks) * 4]) = pv;
        }
        __syncthreads();   // partials visible; all hs reads complete

        // finalize batch bf (gate sums over all 8 k-slices)
        float s0 = 0.f, s1 = 0.f, s2 = 0.f, s3 = 0.f;
        #pragma unroll
        for (int q = 0; q < 8; q++) {
            float4 v = *reinterpret_cast<const float4*>(
                &red[((bf * 16 + u) * RED_PAD + q) * 4]);
            s0 += v.x; s1 += v.y; s2 += v.z; s3 += v.w;
        }
        float f  = sigf(s0 + gxv[0]);
        float i  = sigf(s1 + gxv[1]);
        float o  = sigf(s2 + gxv[2]);
        float cc = tanh_acc(s3 + gxv[3]);
        c_state  = f * c_state + i * cc;
        float h  = o * tanh_acc(c_state);

        g_h[wbuf][(size_t)(b0 + bf) * HID + j] = h;
        __threadfence();   // drains only this thread's g_h store
        __syncthreads();   // all h(t) stores done block-wide

        if (tid == 0) {
            __threadfence();   // cumulativity: block's stores before release
            asm volatile("st.release.gpu.global.u32 [%0], %1;"
                         :: "l"(&g_done[bid]), "r"((unsigned)(t + 1)) : "memory");
        }

        // out stores AFTER release — off the recurrence critical path
        out[((size_t)t * BATCH + b0 + bf) * HID + j] = h;
        if (t == T_LEN - 1) {
            size_t ofs = (size_t)T_LEN * BATCH * HID;
            out[ofs + (size_t)(b0 + bf) * HID + j] = h;
            ofs += (size_t)BATCH * HID;
            out[ofs + (size_t)(b0 + bf) * HID + j] = c_state;
        }
        // next iteration's poll+syncthreads gates all cross-step reads
    }
}

// =====================================================================
// launch
// =====================================================================
extern "C" void kernel_launch(void* const* d_in, const int* in_sizes, int n_in,
                              void* d_out, int out_size) {
    (void)in_sizes; (void)n_in; (void)out_size;
    const float* x  = (const float*)d_in[0];
    const float* Wx = (const float*)d_in[1];
    const float* bx = (const float*)d_in[2];
    const float* Wh = (const float*)d_in[3];
    const float* bh = (const float*)d_in[4];
    float* out = (float*)d_out;

    const int smem1 = 2 * 64 * P1_PAD * sizeof(float);
    const int smem2 = (16 * HS_PAD + 64 * WS_PAD + 16 * 16 * RED_PAD * 4)
                      * sizeof(float);
    cudaFuncSetAttribute(lstm_phase1, cudaFuncAttributeMaxDynamicSharedMemorySize, smem1);
    cudaFuncSetAttribute(lstm_phase2, cudaFuncAttributeMaxDynamicSharedMemorySize, smem2);

    dim3 g1(32, T_LEN);
    lstm_phase1<<<g1, 256, smem1>>>(x, Wx, bx, bh);
    lstm_phase2<<<GRID2, NTHR2, smem2>>>(Wh, out);
}